// round 16
// baseline (speedup 1.0000x reference)
#include <cuda_runtime.h>
#include <cuda_bf16.h>
#include <cstdint>

#define D 64
#define MAX_NODES 100000

// scratch (no cudaMalloc allowed): bf16 neighbor sums + bf16 copy of emb.
// g_nbr invariant: ZEROED at entry of every kernel_launch call
// (.bss zero-init at load; re-zeroed by mlp_hmma_kernel's staging loop).
__device__ __align__(16) __nv_bfloat16 g_nbr[(size_t)MAX_NODES * D];
__device__ __align__(16) __nv_bfloat16 g_embh[(size_t)MAX_NODES * D];

static __device__ __forceinline__ uint32_t pack_bf2(float a, float b) {
    uint32_t r;
    asm("cvt.rn.bf16x2.f32 %0, %1, %2;" : "=r"(r) : "f"(b), "f"(a));  // lo=a, hi=b
    return r;
}

// ---------------------------------------------------------------------------
// K0 prep: emb fp32 -> bf16 convert + zero d_out. (g_nbr zeroing moved to
// the MLP tail — prep is now a pure streaming convert.)
// ---------------------------------------------------------------------------
#define PREP_BLOCKS 2048

__global__ __launch_bounds__(256) void prep_kernel(const float* __restrict__ emb,
                                                   float* __restrict__ out,
                                                   int n_grp) {
    const int tid = blockIdx.x * blockDim.x + threadIdx.x;
    const int stride = PREP_BLOCKS * 256;
    int i = tid;
    for (; i + 3 * stride < n_grp; i += 4 * stride) {
        float4 v0 = __ldg(reinterpret_cast<const float4*>(emb) + i);
        float4 v1 = __ldg(reinterpret_cast<const float4*>(emb) + i + stride);
        float4 v2 = __ldg(reinterpret_cast<const float4*>(emb) + i + 2 * stride);
        float4 v3 = __ldg(reinterpret_cast<const float4*>(emb) + i + 3 * stride);
        uint2 p0, p1, p2, p3;
        p0.x = pack_bf2(v0.x, v0.y); p0.y = pack_bf2(v0.z, v0.w);
        p1.x = pack_bf2(v1.x, v1.y); p1.y = pack_bf2(v1.z, v1.w);
        p2.x = pack_bf2(v2.x, v2.y); p2.y = pack_bf2(v2.z, v2.w);
        p3.x = pack_bf2(v3.x, v3.y); p3.y = pack_bf2(v3.z, v3.w);
        reinterpret_cast<uint2*>(g_embh)[i] = p0;
        reinterpret_cast<uint2*>(g_embh)[i + stride] = p1;
        reinterpret_cast<uint2*>(g_embh)[i + 2 * stride] = p2;
        reinterpret_cast<uint2*>(g_embh)[i + 3 * stride] = p3;
    }
    for (; i < n_grp; i += stride) {
        float4 v = __ldg(reinterpret_cast<const float4*>(emb) + i);
        uint2 pk;
        pk.x = pack_bf2(v.x, v.y);
        pk.y = pack_bf2(v.z, v.w);
        reinterpret_cast<uint2*>(g_embh)[i] = pk;
    }
    if (tid < D / 4) reinterpret_cast<float4*>(out)[tid] = make_float4(0.f, 0.f, 0.f, 0.f);
}

// ---------------------------------------------------------------------------
// K1 scatter: nbr[dst] += emb_bf16[src]  (8 lanes/edge, bf16x2 RED.128).
// REDG-op-rate bound (~1.2 cyc/slice/16B-RED): 12.8M REDs is the floor for
// this decomposition; structure final.
// ---------------------------------------------------------------------------
#define SCAT_BLOCKS 4736

#define RED_BF16X2(p, v) \
    asm volatile("red.global.add.noftz.v4.bf16x2 [%0], {%1,%2,%3,%4};" \
                 :: "l"(p), "r"((v).x), "r"((v).y), "r"((v).z), "r"((v).w) : "memory")

__global__ __launch_bounds__(256) void scatter_kernel(
    const int* __restrict__ src,
    const int* __restrict__ dst,
    int n_items) {
    const int stride = SCAT_BLOCKS * 256;
    int i = blockIdx.x * blockDim.x + threadIdx.x;
    for (; i + stride < n_items; i += 2 * stride) {
        const int i1 = i + stride;
        int e0 = i >> 3,  c0 = i & 7;
        int e1 = i1 >> 3, c1 = i1 & 7;
        int s0 = __ldg(src + e0);
        int d0 = __ldg(dst + e0);
        int s1 = __ldg(src + e1);
        int d1 = __ldg(dst + e1);
        uint4 v0 = *(reinterpret_cast<const uint4*>(g_embh) + (size_t)s0 * 8 + c0);
        uint4 v1 = *(reinterpret_cast<const uint4*>(g_embh) + (size_t)s1 * 8 + c1);
        RED_BF16X2(g_nbr + (size_t)d0 * D + c0 * 8, v0);
        RED_BF16X2(g_nbr + (size_t)d1 * D + c1 * 8, v1);
    }
    if (i < n_items) {
        int e = i >> 3, c = i & 7;
        int s = __ldg(src + e);
        int d = __ldg(dst + e);
        uint4 v = *(reinterpret_cast<const uint4*>(g_embh) + (size_t)s * 8 + c);
        RED_BF16X2(g_nbr + (size_t)d * D + c * 8, v);
    }
}

// ---------------------------------------------------------------------------
// K2: HMMA MLP + relu + graph-sum. Additionally zeroes each g_nbr tile
// right after staging it (restores the invariant for the next replay —
// same thread reads then writes, no cross-thread hazard, tiles unique).
// ---------------------------------------------------------------------------
#define MLP_BLOCKS 592
#define RSTRIDE 272

#define LDSM_X4(r0, r1, r2, r3, addr) \
    asm volatile("ldmatrix.sync.aligned.m8n8.x4.shared.b16 {%0,%1,%2,%3}, [%4];" \
                 : "=r"(r0), "=r"(r1), "=r"(r2), "=r"(r3) : "r"(addr))

#define MMA_BF16(c0, c1, c2, c3, a0, a1, a2, a3, b0, b1) \
    asm volatile("mma.sync.aligned.m16n8k16.row.col.f32.bf16.bf16.f32 " \
                 "{%0,%1,%2,%3}, {%4,%5,%6,%7}, {%8,%9}, {%0,%1,%2,%3};" \
                 : "+f"(c0), "+f"(c1), "+f"(c2), "+f"(c3) \
                 : "r"(a0), "r"(a1), "r"(a2), "r"(a3), "r"(b0), "r"(b1))

__global__ __launch_bounds__(128) void mlp_hmma_kernel(
    const float* __restrict__ feat,
    const float* __restrict__ W1,
    const float* __restrict__ b1,
    const float* __restrict__ W2,
    const float* __restrict__ b2,
    float* __restrict__ out,
    int n_nodes) {

    __shared__ __align__(16) char As[64 * RSTRIDE];
    __shared__ __align__(16) char Bs[64 * RSTRIDE];
    __shared__ float bias[D];
    __shared__ float red[4][D];

    const int t = threadIdx.x;
    const int w = t >> 5;
    const int l = t & 31;

    for (int i = t; i < 1024; i += 128) {
        int o = i >> 4, kg = i & 15;
        float4 a = __ldg(reinterpret_cast<const float4*>(W1) + o * 16 + kg);
        float4 b = __ldg(reinterpret_cast<const float4*>(W2) + o * 16 + kg);
        uint2 pa, pb;
        pa.x = pack_bf2(a.x, a.y); pa.y = pack_bf2(a.z, a.w);
        pb.x = pack_bf2(b.x, b.y); pb.y = pack_bf2(b.z, b.w);
        *reinterpret_cast<uint2*>(Bs + o * RSTRIDE + kg * 8) = pa;
        *reinterpret_cast<uint2*>(Bs + o * RSTRIDE + 128 + kg * 8) = pb;
    }
    if (t < D) bias[t] = __ldg(b1 + t) + __ldg(b2 + t);
    __syncthreads();

    float biasr[8][2];
    #pragma unroll
    for (int f = 0; f < 8; f++) {
        int c0 = f * 8 + (l & 3) * 2;
        biasr[f][0] = bias[c0];
        biasr[f][1] = bias[c0 + 1];
    }

    float colsum[8][2];
    #pragma unroll
    for (int f = 0; f < 8; f++) { colsum[f][0] = 0.f; colsum[f][1] = 0.f; }

    const uint32_t As_u = (uint32_t)__cvta_generic_to_shared(As);
    const uint32_t Bs_u = (uint32_t)__cvta_generic_to_shared(Bs);
    const int quad = l >> 2;

    const int n_tiles = (n_nodes + 63) >> 6;
    for (int tile = blockIdx.x; tile < n_tiles; tile += gridDim.x) {
        const int base = tile << 6;
        __syncthreads();

        #pragma unroll
        for (int j = 0; j < 8; j++) {
            int idx = t + j * 128;
            int row = idx >> 4, kg = idx & 15;
            int v = base + row;
            uint2 p = make_uint2(0u, 0u);
            if (v < n_nodes) {
                float4 x = __ldg(reinterpret_cast<const float4*>(feat) + (size_t)v * 16 + kg);
                p.x = pack_bf2(x.x, x.y);
                p.y = pack_bf2(x.z, x.w);
            }
            *reinterpret_cast<uint2*>(As + row * RSTRIDE + kg * 8) = p;
        }
        #pragma unroll
        for (int j = 0; j < 4; j++) {
            int idx = t + j * 128;
            int row = idx >> 3, c = idx & 7;
            int v = base + row;
            uint4 u = make_uint4(0u, 0u, 0u, 0u);
            if (v < n_nodes) {
                uint4* p = reinterpret_cast<uint4*>(g_nbr) + (size_t)v * 8 + c;
                u = *p;                                   // stage value
                *p = make_uint4(0u, 0u, 0u, 0u);          // re-zero for next replay
            }
            *reinterpret_cast<uint4*>(As + row * RSTRIDE + 128 + c * 16) = u;
        }
        __syncthreads();

        float acc[8][4];
        #pragma unroll
        for (int f = 0; f < 8; f++)
            #pragma unroll
            for (int q = 0; q < 4; q++) acc[f][q] = 0.f;

        #pragma unroll
        for (int s2 = 0; s2 < 4; s2++) {
            uint32_t a0[4], a1[4];
            uint32_t arow = As_u + (w * 16 + (l & 15)) * RSTRIDE + s2 * 64 + ((l >> 4) << 4);
            LDSM_X4(a0[0], a0[1], a0[2], a0[3], arow);
            LDSM_X4(a1[0], a1[1], a1[2], a1[3], arow + 32);
            #pragma unroll
            for (int f = 0; f < 8; f++) {
                uint32_t b[4];
                uint32_t baddr = Bs_u + (f * 8 + (l & 7)) * RSTRIDE + s2 * 64 + ((l >> 3) & 3) * 16;
                LDSM_X4(b[0], b[1], b[2], b[3], baddr);
                MMA_BF16(acc[f][0], acc[f][1], acc[f][2], acc[f][3],
                         a0[0], a0[1], a0[2], a0[3], b[0], b[1]);
                MMA_BF16(acc[f][0], acc[f][1], acc[f][2], acc[f][3],
                         a1[0], a1[1], a1[2], a1[3], b[2], b[3]);
            }
        }

        const bool vlo = (base + w * 16 + quad) < n_nodes;
        const bool vhi = (base + w * 16 + quad + 8) < n_nodes;
        #pragma unroll
        for (int f = 0; f < 8; f++) {
            if (vlo) {
                colsum[f][0] += fmaxf(acc[f][0] + biasr[f][0], 0.f);
                colsum[f][1] += fmaxf(acc[f][1] + biasr[f][1], 0.f);
            }
            if (vhi) {
                colsum[f][0] += fmaxf(acc[f][2] + biasr[f][0], 0.f);
                colsum[f][1] += fmaxf(acc[f][3] + biasr[f][1], 0.f);
            }
        }
    }

    #pragma unroll
    for (int f = 0; f < 8; f++) {
        #pragma unroll
        for (int j = 0; j < 2; j++) {
            float v = colsum[f][j];
            v += __shfl_xor_sync(0xffffffffu, v, 4);
            v += __shfl_xor_sync(0xffffffffu, v, 8);
            v += __shfl_xor_sync(0xffffffffu, v, 16);
            colsum[f][j] = v;
        }
    }
    if (l < 4) {
        #pragma unroll
        for (int f = 0; f < 8; f++) {
            red[w][f * 8 + l * 2 + 0] = colsum[f][0];
            red[w][f * 8 + l * 2 + 1] = colsum[f][1];
        }
    }
    __syncthreads();
    if (t < D) {
        atomicAdd(out + t, red[0][t] + red[1][t] + red[2][t] + red[3][t]);
    }
}

// ---------------------------------------------------------------------------
// launch — inputs (metadata order): feat, emb, W1, b1, W2, b2, edge_src, edge_dst
// 3 launches/call: prep(0), scatter(1), mlp(2). Absolute launch #3 =
// call 2's prep -> ncu profiles the slimmed prep.
// ---------------------------------------------------------------------------
extern "C" void kernel_launch(void* const* d_in, const int* in_sizes, int n_in,
                              void* d_out, int out_size) {
    (void)n_in; (void)out_size;
    const float* feat = (const float*)d_in[0];
    const float* emb  = (const float*)d_in[1];
    const float* W1   = (const float*)d_in[2];
    const float* b1   = (const float*)d_in[3];
    const float* W2   = (const float*)d_in[4];
    const float* b2   = (const float*)d_in[5];
    const int* esrc   = (const int*)d_in[6];
    const int* edst   = (const int*)d_in[7];
    float* out        = (float*)d_out;

    const int n_nodes = in_sizes[0] / D;
    const int n_edges = in_sizes[6];

    // K0 prep (pure convert + out zero)
    prep_kernel<<<PREP_BLOCKS, 256>>>(emb, out, n_nodes * (D / 4));
    // K1 scatter
    scatter_kernel<<<SCAT_BLOCKS, 256>>>(esrc, edst, n_edges * 8);
    // K2 HMMA MLP + graph reduce + g_nbr re-zero
    mlp_hmma_kernel<<<MLP_BLOCKS, 128>>>(feat, W1, b1, W2, b2, out, n_nodes);
}

// round 17
// speedup vs baseline: 1.2870x; 1.2870x over previous
#include <cuda_runtime.h>
#include <cuda_bf16.h>
#include <cstdint>

#define D 64
#define MAX_NODES 100000

// scratch (no cudaMalloc allowed): bf16 neighbor sums + bf16 copy of emb.
// prep zeroes g_nbr every call — this both resets the accumulator AND
// pre-warms L2 with the scatter's atomic-destination lines (load-bearing:
// removing it cost +16us in R16).
__device__ __align__(16) __nv_bfloat16 g_nbr[(size_t)MAX_NODES * D];
__device__ __align__(16) __nv_bfloat16 g_embh[(size_t)MAX_NODES * D];

static __device__ __forceinline__ uint32_t pack_bf2(float a, float b) {
    uint32_t r;
    asm("cvt.rn.bf16x2.f32 %0, %1, %2;" : "=r"(r) : "f"(b), "f"(a));  // lo=a, hi=b
    return r;
}

// ---------------------------------------------------------------------------
// K0 prep: emb fp32 -> bf16, zero g_nbr (16B stores), zero d_out.
// ---------------------------------------------------------------------------
#define PREP_BLOCKS 2048

__global__ __launch_bounds__(256) void prep_kernel(const float* __restrict__ emb,
                                                   float* __restrict__ out,
                                                   int n_grp) {
    const int tid = blockIdx.x * blockDim.x + threadIdx.x;
    const int stride = PREP_BLOCKS * 256;
    // convert stream: 4 independent float4 loads in flight
    int i = tid;
    for (; i + 3 * stride < n_grp; i += 4 * stride) {
        float4 v0 = __ldg(reinterpret_cast<const float4*>(emb) + i);
        float4 v1 = __ldg(reinterpret_cast<const float4*>(emb) + i + stride);
        float4 v2 = __ldg(reinterpret_cast<const float4*>(emb) + i + 2 * stride);
        float4 v3 = __ldg(reinterpret_cast<const float4*>(emb) + i + 3 * stride);
        uint2 p0, p1, p2, p3;
        p0.x = pack_bf2(v0.x, v0.y); p0.y = pack_bf2(v0.z, v0.w);
        p1.x = pack_bf2(v1.x, v1.y); p1.y = pack_bf2(v1.z, v1.w);
        p2.x = pack_bf2(v2.x, v2.y); p2.y = pack_bf2(v2.z, v2.w);
        p3.x = pack_bf2(v3.x, v3.y); p3.y = pack_bf2(v3.z, v3.w);
        reinterpret_cast<uint2*>(g_embh)[i] = p0;
        reinterpret_cast<uint2*>(g_embh)[i + stride] = p1;
        reinterpret_cast<uint2*>(g_embh)[i + 2 * stride] = p2;
        reinterpret_cast<uint2*>(g_embh)[i + 3 * stride] = p3;
    }
    for (; i < n_grp; i += stride) {
        float4 v = __ldg(reinterpret_cast<const float4*>(emb) + i);
        uint2 pk;
        pk.x = pack_bf2(v.x, v.y);
        pk.y = pack_bf2(v.z, v.w);
        reinterpret_cast<uint2*>(g_embh)[i] = pk;
    }
    // zero stream: g_nbr via 16B stores (n_grp/2 uint4 groups)
    const uint4 z4 = make_uint4(0u, 0u, 0u, 0u);
    for (int j = tid; j < n_grp / 2; j += stride) {
        reinterpret_cast<uint4*>(g_nbr)[j] = z4;
    }
    if (tid < D / 4) reinterpret_cast<float4*>(out)[tid] = make_float4(0.f, 0.f, 0.f, 0.f);
}

// ---------------------------------------------------------------------------
// K1 scatter: nbr[dst] += emb_bf16[src]  (8 lanes/edge, bf16x2 RED.128).
// REDG-op-rate bound (~1.2 cyc/slice/16B-RED): 12.8M REDs is the floor for
// this decomposition; structure final.
// ---------------------------------------------------------------------------
#define SCAT_BLOCKS 4736

#define RED_BF16X2(p, v) \
    asm volatile("red.global.add.noftz.v4.bf16x2 [%0], {%1,%2,%3,%4};" \
                 :: "l"(p), "r"((v).x), "r"((v).y), "r"((v).z), "r"((v).w) : "memory")

__global__ __launch_bounds__(256) void scatter_kernel(
    const int* __restrict__ src,
    const int* __restrict__ dst,
    int n_items) {
    const int stride = SCAT_BLOCKS * 256;
    int i = blockIdx.x * blockDim.x + threadIdx.x;
    for (; i + stride < n_items; i += 2 * stride) {
        const int i1 = i + stride;
        int e0 = i >> 3,  c0 = i & 7;
        int e1 = i1 >> 3, c1 = i1 & 7;
        int s0 = __ldg(src + e0);
        int d0 = __ldg(dst + e0);
        int s1 = __ldg(src + e1);
        int d1 = __ldg(dst + e1);
        uint4 v0 = *(reinterpret_cast<const uint4*>(g_embh) + (size_t)s0 * 8 + c0);
        uint4 v1 = *(reinterpret_cast<const uint4*>(g_embh) + (size_t)s1 * 8 + c1);
        RED_BF16X2(g_nbr + (size_t)d0 * D + c0 * 8, v0);
        RED_BF16X2(g_nbr + (size_t)d1 * D + c1 * 8, v1);
    }
    if (i < n_items) {
        int e = i >> 3, c = i & 7;
        int s = __ldg(src + e);
        int d = __ldg(dst + e);
        uint4 v = *(reinterpret_cast<const uint4*>(g_embh) + (size_t)s * 8 + c);
        RED_BF16X2(g_nbr + (size_t)d * D + c * 8, v);
    }
}

// ---------------------------------------------------------------------------
// K2: HMMA MLP + relu + graph-sum (proven ~2.4us).
//   per tile: D[64,64] = A[64,128]bf16 @ B[64,128]bf16^T via mma.sync.
// A row v = [feat[v] | nbr[v]], B row o = [W1[o] | W2[o]], RSTRIDE=272
// keeps ldmatrix conflict-free. Epilogue: +bias, relu, masked column sums,
// shfl reduce, one atomicAdd per dim per CTA.
// ---------------------------------------------------------------------------
#define MLP_BLOCKS 592
#define RSTRIDE 272

#define LDSM_X4(r0, r1, r2, r3, addr) \
    asm volatile("ldmatrix.sync.aligned.m8n8.x4.shared.b16 {%0,%1,%2,%3}, [%4];" \
                 : "=r"(r0), "=r"(r1), "=r"(r2), "=r"(r3) : "r"(addr))

#define MMA_BF16(c0, c1, c2, c3, a0, a1, a2, a3, b0, b1) \
    asm volatile("mma.sync.aligned.m16n8k16.row.col.f32.bf16.bf16.f32 " \
                 "{%0,%1,%2,%3}, {%4,%5,%6,%7}, {%8,%9}, {%0,%1,%2,%3};" \
                 : "+f"(c0), "+f"(c1), "+f"(c2), "+f"(c3) \
                 : "r"(a0), "r"(a1), "r"(a2), "r"(a3), "r"(b0), "r"(b1))

__global__ __launch_bounds__(128) void mlp_hmma_kernel(
    const float* __restrict__ feat,
    const float* __restrict__ W1,
    const float* __restrict__ b1,
    const float* __restrict__ W2,
    const float* __restrict__ b2,
    float* __restrict__ out,
    int n_nodes) {

    __shared__ __align__(16) char As[64 * RSTRIDE];
    __shared__ __align__(16) char Bs[64 * RSTRIDE];
    __shared__ float bias[D];
    __shared__ float red[4][D];

    const int t = threadIdx.x;
    const int w = t >> 5;
    const int l = t & 31;

    for (int i = t; i < 1024; i += 128) {
        int o = i >> 4, kg = i & 15;
        float4 a = __ldg(reinterpret_cast<const float4*>(W1) + o * 16 + kg);
        float4 b = __ldg(reinterpret_cast<const float4*>(W2) + o * 16 + kg);
        uint2 pa, pb;
        pa.x = pack_bf2(a.x, a.y); pa.y = pack_bf2(a.z, a.w);
        pb.x = pack_bf2(b.x, b.y); pb.y = pack_bf2(b.z, b.w);
        *reinterpret_cast<uint2*>(Bs + o * RSTRIDE + kg * 8) = pa;
        *reinterpret_cast<uint2*>(Bs + o * RSTRIDE + 128 + kg * 8) = pb;
    }
    if (t < D) bias[t] = __ldg(b1 + t) + __ldg(b2 + t);
    __syncthreads();

    float biasr[8][2];
    #pragma unroll
    for (int f = 0; f < 8; f++) {
        int c0 = f * 8 + (l & 3) * 2;
        biasr[f][0] = bias[c0];
        biasr[f][1] = bias[c0 + 1];
    }

    float colsum[8][2];
    #pragma unroll
    for (int f = 0; f < 8; f++) { colsum[f][0] = 0.f; colsum[f][1] = 0.f; }

    const uint32_t As_u = (uint32_t)__cvta_generic_to_shared(As);
    const uint32_t Bs_u = (uint32_t)__cvta_generic_to_shared(Bs);
    const int quad = l >> 2;

    const int n_tiles = (n_nodes + 63) >> 6;
    for (int tile = blockIdx.x; tile < n_tiles; tile += gridDim.x) {
        const int base = tile << 6;
        __syncthreads();

        #pragma unroll
        for (int j = 0; j < 8; j++) {
            int idx = t + j * 128;
            int row = idx >> 4, kg = idx & 15;
            int v = base + row;
            uint2 p = make_uint2(0u, 0u);
            if (v < n_nodes) {
                float4 x = __ldg(reinterpret_cast<const float4*>(feat) + (size_t)v * 16 + kg);
                p.x = pack_bf2(x.x, x.y);
                p.y = pack_bf2(x.z, x.w);
            }
            *reinterpret_cast<uint2*>(As + row * RSTRIDE + kg * 8) = p;
        }
        #pragma unroll
        for (int j = 0; j < 4; j++) {
            int idx = t + j * 128;
            int row = idx >> 3, c = idx & 7;
            int v = base + row;
            uint4 u = (v < n_nodes)
                ? *(reinterpret_cast<const uint4*>(g_nbr) + (size_t)v * 8 + c)
                : make_uint4(0u, 0u, 0u, 0u);
            *reinterpret_cast<uint4*>(As + row * RSTRIDE + 128 + c * 16) = u;
        }
        __syncthreads();

        float acc[8][4];
        #pragma unroll
        for (int f = 0; f < 8; f++)
            #pragma unroll
            for (int q = 0; q < 4; q++) acc[f][q] = 0.f;

        #pragma unroll
        for (int s2 = 0; s2 < 4; s2++) {
            uint32_t a0[4], a1[4];
            uint32_t arow = As_u + (w * 16 + (l & 15)) * RSTRIDE + s2 * 64 + ((l >> 4) << 4);
            LDSM_X4(a0[0], a0[1], a0[2], a0[3], arow);
            LDSM_X4(a1[0], a1[1], a1[2], a1[3], arow + 32);
            #pragma unroll
            for (int f = 0; f < 8; f++) {
                uint32_t b[4];
                uint32_t baddr = Bs_u + (f * 8 + (l & 7)) * RSTRIDE + s2 * 64 + ((l >> 3) & 3) * 16;
                LDSM_X4(b[0], b[1], b[2], b[3], baddr);
                MMA_BF16(acc[f][0], acc[f][1], acc[f][2], acc[f][3],
                         a0[0], a0[1], a0[2], a0[3], b[0], b[1]);
                MMA_BF16(acc[f][0], acc[f][1], acc[f][2], acc[f][3],
                         a1[0], a1[1], a1[2], a1[3], b[2], b[3]);
            }
        }

        const bool vlo = (base + w * 16 + quad) < n_nodes;
        const bool vhi = (base + w * 16 + quad + 8) < n_nodes;
        #pragma unroll
        for (int f = 0; f < 8; f++) {
            if (vlo) {
                colsum[f][0] += fmaxf(acc[f][0] + biasr[f][0], 0.f);
                colsum[f][1] += fmaxf(acc[f][1] + biasr[f][1], 0.f);
            }
            if (vhi) {
                colsum[f][0] += fmaxf(acc[f][2] + biasr[f][0], 0.f);
                colsum[f][1] += fmaxf(acc[f][3] + biasr[f][1], 0.f);
            }
        }
    }

    #pragma unroll
    for (int f = 0; f < 8; f++) {
        #pragma unroll
        for (int j = 0; j < 2; j++) {
            float v = colsum[f][j];
            v += __shfl_xor_sync(0xffffffffu, v, 4);
            v += __shfl_xor_sync(0xffffffffu, v, 8);
            v += __shfl_xor_sync(0xffffffffu, v, 16);
            colsum[f][j] = v;
        }
    }
    if (l < 4) {
        #pragma unroll
        for (int f = 0; f < 8; f++) {
            red[w][f * 8 + l * 2 + 0] = colsum[f][0];
            red[w][f * 8 + l * 2 + 1] = colsum[f][1];
        }
    }
    __syncthreads();
    if (t < D) {
        atomicAdd(out + t, red[0][t] + red[1][t] + red[2][t] + red[3][t]);
    }
}

// ---------------------------------------------------------------------------
// launch — inputs (metadata order): feat, emb, W1, b1, W2, b2, edge_src, edge_dst
// 3 launches/call: prep(0), scatter(1), mlp(2).
// ---------------------------------------------------------------------------
extern "C" void kernel_launch(void* const* d_in, const int* in_sizes, int n_in,
                              void* d_out, int out_size) {
    (void)n_in; (void)out_size;
    const float* feat = (const float*)d_in[0];
    const float* emb  = (const float*)d_in[1];
    const float* W1   = (const float*)d_in[2];
    const float* b1   = (const float*)d_in[3];
    const float* W2   = (const float*)d_in[4];
    const float* b2   = (const float*)d_in[5];
    const int* esrc   = (const int*)d_in[6];
    const int* edst   = (const int*)d_in[7];
    float* out        = (float*)d_out;

    const int n_nodes = in_sizes[0] / D;
    const int n_edges = in_sizes[6];

    // K0 prep (convert + g_nbr zero [L2 pre-warm] + out zero)
    prep_kernel<<<PREP_BLOCKS, 256>>>(emb, out, n_nodes * (D / 4));
    // K1 scatter
    scatter_kernel<<<SCAT_BLOCKS, 256>>>(esrc, edst, n_edges * 8);
    // K2 HMMA MLP + graph reduce
    mlp_hmma_kernel<<<MLP_BLOCKS, 128>>>(feat, W1, b1, W2, b2, out, n_nodes);
}